// round 1
// baseline (speedup 1.0000x reference)
#include <cuda_runtime.h>
#include <cstdio>

#define T_DIM 8192
#define C_DIM 2048

// ---------------- scratch (device globals; no allocation allowed) ----------
__device__ float g_kerq[(size_t)T_DIM * C_DIM];   // 64 MB
__device__ float g_kerk[(size_t)T_DIM * C_DIM];   // 64 MB
__device__ float g_v   [(size_t)T_DIM * C_DIM];   // 64 MB
__device__ float g_num [(size_t)T_DIM * C_DIM];   // 64 MB
__device__ float g_zt  [(size_t)T_DIM * C_DIM];   // 64 MB  ((num/den)^T stored [C,T])
__device__ float g_kv  [(size_t)C_DIM * C_DIM];   // 16 MB
__device__ float g_ksum[C_DIM];
__device__ float g_den [T_DIM];

// ---------------- SGEMM: 128x128x8 tile, 256 threads, 8x8 microtile --------
// TRANS_A=false : A is [M,K] row-major
// TRANS_A=true  : A is [K,M] row-major (i.e. compute A^T @ B)
// QKV_EPI=true  : epilogue adds b_attn and writes kerq/kerk/v feature maps
constexpr int BM = 128, BN = 128, BK = 8, TM = 8, TN = 8;

template <bool TRANS_A, bool QKV_EPI>
__global__ __launch_bounds__(256)
void sgemm_kernel(const float* __restrict__ A,
                  const float* __restrict__ B,
                  const float* __restrict__ bias,   // may be nullptr
                  float* __restrict__ Cout,         // unused if QKV_EPI
                  int M, int N, int K,
                  const float* __restrict__ gq, const float* __restrict__ bq,
                  const float* __restrict__ gk, const float* __restrict__ bk)
{
    __shared__ float As[BK][BM];
    __shared__ float Bs[BK][BN];

    const int tid = threadIdx.x;
    const int bm  = blockIdx.y * BM;
    const int bn  = blockIdx.x * BN;
    const int tx  = tid & 15;
    const int ty  = tid >> 4;

    float acc[TM][TN];
#pragma unroll
    for (int i = 0; i < TM; i++)
#pragma unroll
        for (int j = 0; j < TN; j++) acc[i][j] = 0.f;

    const float* Aptr;
    if (!TRANS_A) {
        // each thread loads one float4 of a 128x8 tile: row=tid>>1, col4=(tid&1)*4
        Aptr = A + (size_t)(bm + (tid >> 1)) * K + (tid & 1) * 4;
    } else {
        // tile is 8 rows (k) x 128 cols (m): row=tid>>5, col4=(tid&31)*4
        Aptr = A + (size_t)(tid >> 5) * M + bm + (tid & 31) * 4;
    }
    const float* Bptr = B + (size_t)(tid >> 5) * N + bn + (tid & 31) * 4;

    for (int k0 = 0; k0 < K; k0 += BK) {
        float4 av = *(const float4*)Aptr;
        float4 bv = *(const float4*)Bptr;
        if (!TRANS_A) {
            const int r  = tid >> 1;
            const int c4 = (tid & 1) * 4;
            As[c4 + 0][r] = av.x;
            As[c4 + 1][r] = av.y;
            As[c4 + 2][r] = av.z;
            As[c4 + 3][r] = av.w;
            Aptr += BK;
        } else {
            *(float4*)&As[tid >> 5][(tid & 31) * 4] = av;
            Aptr += (size_t)BK * M;
        }
        *(float4*)&Bs[tid >> 5][(tid & 31) * 4] = bv;
        Bptr += (size_t)BK * N;
        __syncthreads();

#pragma unroll
        for (int kk = 0; kk < BK; kk++) {
            float a[TM], b[TN];
            *(float4*)&a[0] = *(const float4*)&As[kk][ty * TM];
            *(float4*)&a[4] = *(const float4*)&As[kk][ty * TM + 4];
            *(float4*)&b[0] = *(const float4*)&Bs[kk][tx * TN];
            *(float4*)&b[4] = *(const float4*)&Bs[kk][tx * TN + 4];
#pragma unroll
            for (int i = 0; i < TM; i++)
#pragma unroll
                for (int j = 0; j < TN; j++)
                    acc[i][j] += a[i] * b[j];
        }
        __syncthreads();
    }

    if (QKV_EPI) {
        // whole 128-wide block lies within one third of the 3C output
        const int sel = (bn >= 2 * C_DIM) ? 2 : ((bn >= C_DIM) ? 1 : 0);
#pragma unroll
        for (int i = 0; i < TM; i++) {
            const int gm = bm + ty * TM + i;
#pragma unroll
            for (int j = 0; j < TN; j++) {
                const int gn = bn + tx * TN + j;
                const int nl = gn - sel * C_DIM;
                float val = acc[i][j] + bias[gn];
                if (sel == 0) {
                    float u = gq[nl] * val + bq[nl];
                    g_kerq[(size_t)gm * C_DIM + nl] = u * u;
                } else if (sel == 1) {
                    float u = gk[nl] * val + bk[nl];
                    g_kerk[(size_t)gm * C_DIM + nl] = u * u;
                } else {
                    g_v[(size_t)gm * C_DIM + nl] = val;
                }
            }
        }
    } else {
#pragma unroll
        for (int i = 0; i < TM; i++) {
            const int gm = bm + ty * TM + i;
            if (bias) {
#pragma unroll
                for (int j = 0; j < TN; j++)
                    acc[i][j] += bias[bn + tx * TN + j];
            }
            *(float4*)&Cout[(size_t)gm * N + bn + tx * TN]     = *(float4*)&acc[i][0];
            *(float4*)&Cout[(size_t)gm * N + bn + tx * TN + 4] = *(float4*)&acc[i][4];
        }
    }
}

// ---------------- ksum: column sums of kerk --------------------------------
__global__ void zero_ksum_kernel()
{
    int i = blockIdx.x * blockDim.x + threadIdx.x;
    if (i < C_DIM) g_ksum[i] = 0.f;
}

__global__ void ksum_kernel()
{
    // grid (C/256, 64): each block sums a 128-row chunk for 256 columns
    int c  = blockIdx.x * 256 + threadIdx.x;
    int t0 = blockIdx.y * 128;
    float s = 0.f;
    for (int t = t0; t < t0 + 128; t++)
        s += g_kerk[(size_t)t * C_DIM + c];
    atomicAdd(&g_ksum[c], s);
}

// ---------------- den[t] = kerq[t,:] . ksum --------------------------------
__global__ __launch_bounds__(256)
void den_kernel()
{
    int t = blockIdx.x;
    float s = 0.f;
    for (int c = threadIdx.x; c < C_DIM; c += 256)
        s += g_kerq[(size_t)t * C_DIM + c] * g_ksum[c];
    // reduce 256 -> 1
    __shared__ float red[8];
#pragma unroll
    for (int off = 16; off; off >>= 1)
        s += __shfl_down_sync(0xffffffffu, s, off);
    if ((threadIdx.x & 31) == 0) red[threadIdx.x >> 5] = s;
    __syncthreads();
    if (threadIdx.x == 0) {
        float tot = 0.f;
#pragma unroll
        for (int w = 0; w < 8; w++) tot += red[w];
        g_den[t] = tot;
    }
}

// ---------------- zt[c,t] = num[t,c] / den[t]  (32x32 smem transpose) ------
__global__ void tdiv_kernel()
{
    __shared__ float tile[32][33];
    const int c  = blockIdx.x * 32 + threadIdx.x;
    const int by = blockIdx.y * 32;
#pragma unroll
    for (int i = 0; i < 32; i += 8) {
        int t = by + threadIdx.y + i;
        tile[threadIdx.y + i][threadIdx.x] =
            g_num[(size_t)t * C_DIM + c] / g_den[t];
    }
    __syncthreads();
    const int t2 = by + threadIdx.x;
#pragma unroll
    for (int i = 0; i < 32; i += 8) {
        int c2 = blockIdx.x * 32 + threadIdx.y + i;
        g_zt[(size_t)c2 * T_DIM + t2] = tile[threadIdx.x][threadIdx.y + i];
    }
}

// ---------------- launch ---------------------------------------------------
extern "C" void kernel_launch(void* const* d_in, const int* in_sizes, int n_in,
                              void* d_out, int out_size)
{
    const float* x      = (const float*)d_in[0];
    const float* w_attn = (const float*)d_in[1];
    const float* b_attn = (const float*)d_in[2];
    const float* gq     = (const float*)d_in[3];
    const float* bq     = (const float*)d_in[4];
    const float* gk     = (const float*)d_in[5];
    const float* bk     = (const float*)d_in[6];
    const float* w_out  = (const float*)d_in[7];
    const float* b_out  = (const float*)d_in[8];
    float* out = (float*)d_out;

    float *p_kerq, *p_kerk, *p_v, *p_num, *p_zt, *p_kv;
    cudaGetSymbolAddress((void**)&p_kerq, g_kerq);
    cudaGetSymbolAddress((void**)&p_kerk, g_kerk);
    cudaGetSymbolAddress((void**)&p_v,    g_v);
    cudaGetSymbolAddress((void**)&p_num,  g_num);
    cudaGetSymbolAddress((void**)&p_zt,   g_zt);
    cudaGetSymbolAddress((void**)&p_kv,   g_kv);

    // 1) qkv = x@w_attn + b_attn, fused feature maps -> kerq, kerk, v
    {
        dim3 grid(3 * C_DIM / BN, T_DIM / BM);
        sgemm_kernel<false, true><<<grid, 256>>>(
            x, w_attn, b_attn, nullptr,
            T_DIM, 3 * C_DIM, C_DIM, gq, bq, gk, bk);
    }
    // 2) ksum = sum_t kerk[t,:]
    zero_ksum_kernel<<<C_DIM / 256, 256>>>();
    {
        dim3 grid(C_DIM / 256, T_DIM / 128);
        ksum_kernel<<<grid, 256>>>();
    }
    // 3) kv = kerk^T @ v   (A stored [K=T, M=C])
    {
        dim3 grid(C_DIM / BN, C_DIM / BM);
        sgemm_kernel<true, false><<<grid, 256>>>(
            p_kerk, p_v, nullptr, p_kv,
            C_DIM, C_DIM, T_DIM, nullptr, nullptr, nullptr, nullptr);
    }
    // 4) num = kerq @ kv
    {
        dim3 grid(C_DIM / BN, T_DIM / BM);
        sgemm_kernel<false, false><<<grid, 256>>>(
            p_kerq, p_kv, nullptr, p_num,
            T_DIM, C_DIM, C_DIM, nullptr, nullptr, nullptr, nullptr);
    }
    // 5) den[t] = kerq[t,:] . ksum
    den_kernel<<<T_DIM, 256>>>();
    // 6) zt[c,t] = num[t,c]/den[t]  (the transpose(1,2).view reinterpretation)
    {
        dim3 grid(C_DIM / 32, T_DIM / 32);
        tdiv_kernel<<<grid, dim3(32, 8)>>>();
    }
    // 7) out = view(zt,[T,C]) @ w_out + b_out
    {
        dim3 grid(C_DIM / BN, T_DIM / BM);
        sgemm_kernel<false, false><<<grid, 256>>>(
            p_zt, w_out, b_out, out,
            T_DIM, C_DIM, C_DIM, nullptr, nullptr, nullptr, nullptr);
    }
    (void)in_sizes; (void)n_in; (void)out_size;
}

// round 3
// speedup vs baseline: 2.0186x; 2.0186x over previous
#include <cuda_runtime.h>
#include <cstdint>

#define T_DIM 8192
#define C_DIM 2048

// ---------------- scratch (device globals; no allocation allowed) ----------
__device__ float g_xr   [(size_t)T_DIM * C_DIM];      // x rounded to tf32
__device__ float g_kerq [(size_t)T_DIM * C_DIM];      // [T,C]
__device__ float g_kerk [(size_t)T_DIM * C_DIM];      // [T,C]
__device__ float g_v    [(size_t)T_DIM * C_DIM];      // [T,C]
__device__ float g_num  [(size_t)T_DIM * C_DIM];      // [T,C]
__device__ float g_zt   [(size_t)C_DIM * T_DIM];      // [C,T] = (num/den)^T
__device__ float g_kv   [(size_t)C_DIM * C_DIM];      // [C,C]
__device__ float g_war  [(size_t)C_DIM * 3 * C_DIM];  // w_attn rounded
__device__ float g_wor  [(size_t)C_DIM * C_DIM];      // w_out rounded
__device__ float g_ksum [C_DIM];
__device__ float g_den  [T_DIM];

// ---------------- helpers ---------------------------------------------------
__device__ __forceinline__ uint32_t smem_u32(const void* p) {
    uint32_t a;
    asm("{ .reg .u64 t; cvta.to.shared.u64 t, %1; cvt.u32.u64 %0, t; }" : "=r"(a) : "l"(p));
    return a;
}
__device__ __forceinline__ float rna_tf32(float x) {
    uint32_t u;
    asm("cvt.rna.tf32.f32 %0, %1;" : "=r"(u) : "f"(x));
    return __uint_as_float(u);
}
__device__ __forceinline__ void cp_async16(uint32_t s, const float* g) {
    asm volatile("cp.async.cg.shared.global [%0], [%1], 16;\n" :: "r"(s), "l"(g) : "memory");
}
__device__ __forceinline__ void cp_commit() {
    asm volatile("cp.async.commit_group;\n" ::: "memory");
}
__device__ __forceinline__ void cp_wait2() {
    asm volatile("cp.async.wait_group 2;\n" ::: "memory");
}
#define MMA_TF32(d, a, b) \
    asm volatile("mma.sync.aligned.m16n8k8.row.col.f32.tf32.tf32.f32 " \
        "{%0,%1,%2,%3}, {%4,%5,%6,%7}, {%8,%9}, {%0,%1,%2,%3};" \
        : "+f"((d)[0]), "+f"((d)[1]), "+f"((d)[2]), "+f"((d)[3]) \
        : "r"((a)[0]), "r"((a)[1]), "r"((a)[2]), "r"((a)[3]), "r"((b)[0]), "r"((b)[1]))

// ---------------- tf32 mma.sync GEMM ----------------------------------------
// D[M,N] = A @ B.  A: KMAJOR(gmem [M,K], lda=K-stride) or MMAJOR(gmem [K,M], lda=M-stride).
// B always [K,N] gmem (ldb = N-stride).
constexpr int BM = 128, BN = 128, BK = 32, STAGES = 4;
constexpr int SA_K = 36;                 // floats/row, A KMAJOR [128][36]
constexpr int SA_M = 132;                // floats/row, A MMAJOR [32][132]
constexpr int SB   = 132;                // floats/row, B [32][132]
constexpr int A_FLOATS = 128 * 36;       // 4608 (covers both variants)
constexpr int B_FLOATS = 32 * 132;       // 4224
constexpr int STG_FLOATS = A_FLOATS + B_FLOATS;       // 8832
constexpr int SMEM_BYTES = STAGES * STG_FLOATS * 4;   // 141312

// EPI: 0 = qkv feature maps, 1 = rna store, 2 = +bias fp32 store
template <int AMAJOR, int EPI>
__global__ __launch_bounds__(256, 1)
void mma_gemm(const float* __restrict__ A, const float* __restrict__ B,
              const float* __restrict__ bias,
              float* __restrict__ O0, float* __restrict__ O1, float* __restrict__ O2,
              const float* __restrict__ gq, const float* __restrict__ bq,
              const float* __restrict__ gk, const float* __restrict__ bk,
              int N, int K, int lda, int ldb)
{
    extern __shared__ float sm[];
    const uint32_t sb = smem_u32(sm);
    const int tid  = threadIdx.x;
    const int lane = tid & 31;
    const int wid  = tid >> 5;
    const int wm   = wid & 3;            // 4 warps over M
    const int wn   = wid >> 2;           // 2 warps over N
    const int tg   = lane >> 2;          // 0..7
    const int tq   = lane & 3;           // 0..3
    const int bm   = blockIdx.y * BM;
    const int bn   = blockIdx.x * BN;
    const int NK   = K / BK;

    float acc[2][8][4];
#pragma unroll
    for (int i = 0; i < 2; i++)
#pragma unroll
        for (int j = 0; j < 8; j++)
#pragma unroll
            for (int r = 0; r < 4; r++) acc[i][j][r] = 0.f;

    auto load_stage = [&](int chunk, int stage) {
        const uint32_t base = sb + (uint32_t)stage * STG_FLOATS * 4;
        if (AMAJOR == 0) {
            const int m  = tid >> 1;
            const int q0 = (tid & 1) * 4;          // granule index (16B units)
            const float* g = A + (size_t)(bm + m) * lda + chunk * BK + q0 * 4;
            const uint32_t d = base + (uint32_t)(m * SA_K * 4) + q0 * 16;
#pragma unroll
            for (int i = 0; i < 4; i++) cp_async16(d + i * 16, g + i * 4);
        } else {
            const int k  = tid >> 3;
            const int q0 = (tid & 7) * 4;
            const float* g = A + (size_t)(chunk * BK + k) * lda + bm + q0 * 4;
            const uint32_t d = base + (uint32_t)(k * SA_M * 4) + q0 * 16;
#pragma unroll
            for (int i = 0; i < 4; i++) cp_async16(d + i * 16, g + i * 4);
        }
        {
            const int k  = tid >> 3;
            const int q0 = (tid & 7) * 4;
            const float* g = B + (size_t)(chunk * BK + k) * ldb + bn + q0 * 4;
            const uint32_t d = base + A_FLOATS * 4 + (uint32_t)(k * SB * 4) + q0 * 16;
#pragma unroll
            for (int i = 0; i < 4; i++) cp_async16(d + i * 16, g + i * 4);
        }
        cp_commit();
    };

    load_stage(0, 0);
    load_stage(1, 1);
    load_stage(2, 2);

    const int rbase = wm * 32 + tg;
    const int nbase = wn * 64 + tg;

    for (int i = 0; i < NK; i++) {
        cp_wait2();                 // group i complete (always-commit keeps counts uniform)
        __syncthreads();
        if (i + 3 < NK) load_stage(i + 3, (i + 3) % STAGES);
        else            cp_commit();  // empty group keeps wait_group accounting uniform

        const uint32_t* sA = (const uint32_t*)(sm + (size_t)(i % STAGES) * STG_FLOATS);
        const uint32_t* sB2 = sA + A_FLOATS;

#pragma unroll
        for (int ks = 0; ks < 4; ks++) {
            const int kb = ks * 8;
            uint32_t a[2][4], b[8][2];
            if (AMAJOR == 0) {
#pragma unroll
                for (int mi = 0; mi < 2; mi++) {
                    const int r = rbase + mi * 16;
                    a[mi][0] = sA[(r)     * SA_K + kb + tq];
                    a[mi][1] = sA[(r + 8) * SA_K + kb + tq];
                    a[mi][2] = sA[(r)     * SA_K + kb + tq + 4];
                    a[mi][3] = sA[(r + 8) * SA_K + kb + tq + 4];
                }
            } else {
#pragma unroll
                for (int mi = 0; mi < 2; mi++) {
                    const int r = rbase + mi * 16;
                    a[mi][0] = sA[(kb + tq)     * SA_M + r];
                    a[mi][1] = sA[(kb + tq)     * SA_M + r + 8];
                    a[mi][2] = sA[(kb + tq + 4) * SA_M + r];
                    a[mi][3] = sA[(kb + tq + 4) * SA_M + r + 8];
                }
            }
#pragma unroll
            for (int ni = 0; ni < 8; ni++) {
                b[ni][0] = sB2[(kb + tq)     * SB + nbase + ni * 8];
                b[ni][1] = sB2[(kb + tq + 4) * SB + nbase + ni * 8];
            }
#pragma unroll
            for (int mi = 0; mi < 2; mi++)
#pragma unroll
                for (int ni = 0; ni < 8; ni++)
                    MMA_TF32(acc[mi][ni], a[mi], b[ni]);
        }
    }
    __syncthreads();

    // ---------------- epilogue (all natural, coalesced float2 stores) -------
#pragma unroll
    for (int mi = 0; mi < 2; mi++) {
#pragma unroll
        for (int h = 0; h < 2; h++) {
            const int m = bm + wm * 32 + mi * 16 + h * 8 + tg;
            if (EPI == 0) {
                const int sel = bn >> 11;             // 3C split, BN=128 divides C
                const int nl0 = bn - sel * C_DIM + wn * 64 + 2 * tq;
#pragma unroll
                for (int ni = 0; ni < 8; ni++) {
                    const int nl = nl0 + ni * 8;
                    const int gn = bn + wn * 64 + ni * 8 + 2 * tq;
                    float v0 = acc[mi][ni][2 * h]     + bias[gn];
                    float v1 = acc[mi][ni][2 * h + 1] + bias[gn + 1];
                    float2 o;
                    if (sel == 0) {
                        float u0 = gq[nl] * v0 + bq[nl];
                        float u1 = gq[nl + 1] * v1 + bq[nl + 1];
                        o.x = rna_tf32(u0 * u0); o.y = rna_tf32(u1 * u1);
                        *(float2*)&O0[(size_t)m * C_DIM + nl] = o;
                    } else if (sel == 1) {
                        float u0 = gk[nl] * v0 + bk[nl];
                        float u1 = gk[nl + 1] * v1 + bk[nl + 1];
                        o.x = rna_tf32(u0 * u0); o.y = rna_tf32(u1 * u1);
                        *(float2*)&O1[(size_t)m * C_DIM + nl] = o;
                    } else {
                        o.x = rna_tf32(v0); o.y = rna_tf32(v1);
                        *(float2*)&O2[(size_t)m * C_DIM + nl] = o;
                    }
                }
            } else if (EPI == 1) {
#pragma unroll
                for (int ni = 0; ni < 8; ni++) {
                    const int n = bn + wn * 64 + ni * 8 + 2 * tq;
                    float2 o;
                    o.x = rna_tf32(acc[mi][ni][2 * h]);
                    o.y = rna_tf32(acc[mi][ni][2 * h + 1]);
                    *(float2*)&O0[(size_t)m * N + n] = o;
                }
            } else {
#pragma unroll
                for (int ni = 0; ni < 8; ni++) {
                    const int n = bn + wn * 64 + ni * 8 + 2 * tq;
                    float2 o;
                    o.x = acc[mi][ni][2 * h]     + bias[n];
                    o.y = acc[mi][ni][2 * h + 1] + bias[n + 1];
                    *(float2*)&O0[(size_t)m * N + n] = o;
                }
            }
        }
    }
}

// ---------------- aux kernels ------------------------------------------------
__global__ void round_copy_kernel(const float* __restrict__ in, float* __restrict__ out, int n4)
{
    int i = blockIdx.x * blockDim.x + threadIdx.x;
    if (i < n4) {
        float4 v = ((const float4*)in)[i];
        v.x = rna_tf32(v.x); v.y = rna_tf32(v.y);
        v.z = rna_tf32(v.z); v.w = rna_tf32(v.w);
        ((float4*)out)[i] = v;
    }
}

__global__ void zero_ksum_kernel()
{
    int i = blockIdx.x * blockDim.x + threadIdx.x;
    if (i < C_DIM) g_ksum[i] = 0.f;
}

__global__ void ksum_kernel()
{
    int c  = blockIdx.x * 256 + threadIdx.x;
    int t0 = blockIdx.y * 128;
    float s = 0.f;
    for (int t = t0; t < t0 + 128; t++)
        s += g_kerk[(size_t)t * C_DIM + c];
    atomicAdd(&g_ksum[c], s);
}

__global__ __launch_bounds__(256)
void den_kernel()
{
    const int t = blockIdx.x;
    float s = 0.f;
    for (int c = threadIdx.x; c < C_DIM; c += 256)
        s += g_kerq[(size_t)t * C_DIM + c] * g_ksum[c];
    __shared__ float red[8];
#pragma unroll
    for (int off = 16; off; off >>= 1) s += __shfl_down_sync(0xffffffffu, s, off);
    if ((threadIdx.x & 31) == 0) red[threadIdx.x >> 5] = s;
    __syncthreads();
    if (threadIdx.x == 0) {
        float tot = 0.f;
#pragma unroll
        for (int w = 0; w < 8; w++) tot += red[w];
        g_den[t] = tot;
    }
}

// zt[c,t] = rna(num[t,c] / den[t])
__global__ void tdiv_kernel()
{
    __shared__ float tile[32][33];
    const int c  = blockIdx.x * 32 + threadIdx.x;
    const int by = blockIdx.y * 32;
#pragma unroll
    for (int i = 0; i < 32; i += 8) {
        int t = by + threadIdx.y + i;
        tile[threadIdx.y + i][threadIdx.x] =
            rna_tf32(g_num[(size_t)t * C_DIM + c] / g_den[t]);
    }
    __syncthreads();
    const int t2 = by + threadIdx.x;
#pragma unroll
    for (int i = 0; i < 32; i += 8) {
        int c2 = blockIdx.x * 32 + threadIdx.y + i;
        g_zt[(size_t)c2 * T_DIM + t2] = tile[threadIdx.x][threadIdx.y + i];
    }
}

// ---------------- launch -----------------------------------------------------
extern "C" void kernel_launch(void* const* d_in, const int* in_sizes, int n_in,
                              void* d_out, int out_size)
{
    const float* x      = (const float*)d_in[0];
    const float* w_attn = (const float*)d_in[1];
    const float* b_attn = (const float*)d_in[2];
    const float* gq     = (const float*)d_in[3];
    const float* bq     = (const float*)d_in[4];
    const float* gk     = (const float*)d_in[5];
    const float* bk     = (const float*)d_in[6];
    const float* w_out  = (const float*)d_in[7];
    const float* b_out  = (const float*)d_in[8];
    float* out = (float*)d_out;

    float *p_xr, *p_kerq, *p_kerk, *p_v, *p_num, *p_zt, *p_kv, *p_war, *p_wor;
    cudaGetSymbolAddress((void**)&p_xr,   g_xr);
    cudaGetSymbolAddress((void**)&p_kerq, g_kerq);
    cudaGetSymbolAddress((void**)&p_kerk, g_kerk);
    cudaGetSymbolAddress((void**)&p_v,    g_v);
    cudaGetSymbolAddress((void**)&p_num,  g_num);
    cudaGetSymbolAddress((void**)&p_zt,   g_zt);
    cudaGetSymbolAddress((void**)&p_kv,   g_kv);
    cudaGetSymbolAddress((void**)&p_war,  g_war);
    cudaGetSymbolAddress((void**)&p_wor,  g_wor);

    cudaFuncSetAttribute(mma_gemm<0, 0>, cudaFuncAttributeMaxDynamicSharedMemorySize, SMEM_BYTES);
    cudaFuncSetAttribute(mma_gemm<1, 1>, cudaFuncAttributeMaxDynamicSharedMemorySize, SMEM_BYTES);
    cudaFuncSetAttribute(mma_gemm<0, 1>, cudaFuncAttributeMaxDynamicSharedMemorySize, SMEM_BYTES);
    cudaFuncSetAttribute(mma_gemm<0, 2>, cudaFuncAttributeMaxDynamicSharedMemorySize, SMEM_BYTES);

    // prep: tf32-round inputs (no transposes needed with mma.sync addressing)
    round_copy_kernel<<<(T_DIM * C_DIM / 4 + 255) / 256, 256>>>(x, p_xr, T_DIM * C_DIM / 4);
    round_copy_kernel<<<(3 * C_DIM * C_DIM / 4 + 255) / 256, 256>>>(w_attn, p_war, 3 * C_DIM * C_DIM / 4);
    round_copy_kernel<<<(C_DIM * C_DIM / 4 + 255) / 256, 256>>>(w_out, p_wor, C_DIM * C_DIM / 4);

    // 1) qkv = x @ w_attn + b : feature maps -> kerq, kerk, v (all [T,C])
    {
        dim3 grid(3 * C_DIM / BN, T_DIM / BM);
        mma_gemm<0, 0><<<grid, 256, SMEM_BYTES>>>(
            p_xr, p_war, b_attn, p_kerq, p_kerk, p_v,
            gq, bq, gk, bk, 3 * C_DIM, C_DIM, C_DIM, 3 * C_DIM);
    }
    // 2) ksum, den
    zero_ksum_kernel<<<C_DIM / 256, 256>>>();
    {
        dim3 grid(C_DIM / 256, T_DIM / 128);
        ksum_kernel<<<grid, 256>>>();
    }
    den_kernel<<<T_DIM, 256>>>();
    // 3) kv = kerk^T @ v   (A MMAJOR: gmem [K=T, M=C])
    {
        dim3 grid(C_DIM / BN, C_DIM / BM);
        mma_gemm<1, 1><<<grid, 256, SMEM_BYTES>>>(
            p_kerk, p_v, nullptr, p_kv, nullptr, nullptr,
            nullptr, nullptr, nullptr, nullptr, C_DIM, T_DIM, C_DIM, C_DIM);
    }
    // 4) num = kerq @ kv
    {
        dim3 grid(C_DIM / BN, T_DIM / BM);
        mma_gemm<0, 1><<<grid, 256, SMEM_BYTES>>>(
            p_kerq, p_kv, nullptr, p_num, nullptr, nullptr,
            nullptr, nullptr, nullptr, nullptr, C_DIM, C_DIM, C_DIM, C_DIM);
    }
    // 5) zt = (num/den)^T  (the transpose(1,2).view reinterpretation)
    {
        dim3 grid(C_DIM / 32, T_DIM / 32);
        tdiv_kernel<<<grid, dim3(32, 8)>>>();
    }
    // 6) out = view(zt,[T,C]) @ w_out + b_out
    {
        dim3 grid(C_DIM / BN, T_DIM / BM);
        mma_gemm<0, 2><<<grid, 256, SMEM_BYTES>>>(
            p_zt, p_wor, b_out, out, nullptr, nullptr,
            nullptr, nullptr, nullptr, nullptr, C_DIM, C_DIM, C_DIM, C_DIM);
    }
    (void)in_sizes; (void)n_in; (void)out_size;
}

// round 4
// speedup vs baseline: 5.2263x; 2.5891x over previous
#include <cuda_runtime.h>
#include <cuda_fp16.h>
#include <cstdint>

#define T_DIM 8192
#define C_DIM 2048

// ---------------- scratch (device globals; no allocation allowed) ----------
__device__ __half g_xh   [(size_t)T_DIM * C_DIM];      // x  [T,C] half
__device__ __half g_waT  [(size_t)3 * C_DIM * C_DIM];  // w_attn^T [3C,C]
__device__ __half g_woT  [(size_t)C_DIM * C_DIM];      // w_out^T  [C,C]
__device__ __half g_kerq [(size_t)T_DIM * C_DIM];      // [T,C]
__device__ __half g_kerkT[(size_t)C_DIM * T_DIM];      // [C,T]
__device__ __half g_vT   [(size_t)C_DIM * T_DIM];      // [C,T]
__device__ __half g_kvT  [(size_t)C_DIM * C_DIM];      // [C,C]  kvT[d,c]
__device__ __half g_zt   [(size_t)C_DIM * T_DIM];      // [C,T] -> viewed [T,C]
__device__ float  g_num  [(size_t)T_DIM * C_DIM];      // [T,C] fp32
__device__ float  g_ksum [C_DIM];
__device__ float  g_den  [T_DIM];

// ---------------- helpers ---------------------------------------------------
__device__ __forceinline__ uint32_t smem_u32(const void* p) {
    uint32_t a;
    asm("{ .reg .u64 t; cvta.to.shared.u64 t, %1; cvt.u32.u64 %0, t; }" : "=r"(a) : "l"(p));
    return a;
}
__device__ __forceinline__ void cp_async16(uint32_t s, const void* g) {
    asm volatile("cp.async.cg.shared.global [%0], [%1], 16;\n" :: "r"(s), "l"(g) : "memory");
}
__device__ __forceinline__ void cp_commit() {
    asm volatile("cp.async.commit_group;\n" ::: "memory");
}
__device__ __forceinline__ void cp_wait2() {
    asm volatile("cp.async.wait_group 2;\n" ::: "memory");
}
#define MMA_F16(d, a, b) \
    asm volatile("mma.sync.aligned.m16n8k16.row.col.f32.f16.f16.f32 " \
        "{%0,%1,%2,%3}, {%4,%5,%6,%7}, {%8,%9}, {%0,%1,%2,%3};" \
        : "+f"((d)[0]), "+f"((d)[1]), "+f"((d)[2]), "+f"((d)[3]) \
        : "r"((a)[0]), "r"((a)[1]), "r"((a)[2]), "r"((a)[3]), "r"((b)[0]), "r"((b)[1]))

// ---------------- fp16 mma.sync GEMM ----------------------------------------
// D[M,N] = A @ B^T with A [M,K] and B [N,K], both half row-major over K.
constexpr int BM = 128, BN = 128, BK = 32, STAGES = 4;
constexpr int RSTR      = 40;                 // halves per smem row (32 + 8 pad)
constexpr int OP_HALVES = 128 * RSTR;         // 5120
constexpr int STG_HALVES = 2 * OP_HALVES;     // 10240
constexpr int SMEM_BYTES = STAGES * STG_HALVES * 2;  // 81920

// EPI: 0 = qkv feature maps, 1 = half2 natural (kvT), 2 = fp32 natural (num),
//      3 = fp32 natural + bias (out)
template <int EPI>
__global__ __launch_bounds__(256, 2)
void mma_gemm(const __half* __restrict__ A, const __half* __restrict__ B,
              const float* __restrict__ bias,
              void* __restrict__ O0, __half* __restrict__ O1, __half* __restrict__ O2,
              const float* __restrict__ gq, const float* __restrict__ bq,
              const float* __restrict__ gk, const float* __restrict__ bk,
              int N, int K)
{
    extern __shared__ __half sm[];
    const uint32_t sb = smem_u32(sm);
    const int tid  = threadIdx.x;
    const int lane = tid & 31;
    const int wid  = tid >> 5;
    const int wm   = wid & 3;            // 4 warps over M (32 rows each)
    const int wn   = wid >> 2;           // 2 warps over N (64 cols each)
    const int tg   = lane >> 2;          // 0..7
    const int tq   = lane & 3;           // 0..3
    const int bm   = blockIdx.y * BM;
    const int bn   = blockIdx.x * BN;
    const int NK   = K / BK;

    float acc[2][8][4];
#pragma unroll
    for (int i = 0; i < 2; i++)
#pragma unroll
        for (int j = 0; j < 8; j++)
#pragma unroll
            for (int r = 0; r < 4; r++) acc[i][j][r] = 0.f;

    const int lr = tid >> 1;             // row 0..127
    const int g0 = (tid & 1) * 2;        // first granule (16B units) of 2

    auto load_stage = [&](int chunk, int stage) {
        const uint32_t base = sb + (uint32_t)stage * STG_HALVES * 2;
        const __half* gA = A + (size_t)(bm + lr) * K + chunk * BK + g0 * 8;
        const __half* gB = B + (size_t)(bn + lr) * K + chunk * BK + g0 * 8;
        const uint32_t dA = base + (uint32_t)(lr * RSTR + g0 * 8) * 2;
        const uint32_t dB = dA + OP_HALVES * 2;
        cp_async16(dA,      gA);
        cp_async16(dA + 16, gA + 8);
        cp_async16(dB,      gB);
        cp_async16(dB + 16, gB + 8);
        cp_commit();
    };

    load_stage(0, 0);
    load_stage(1, 1);
    load_stage(2, 2);

    const int rbase = wm * 32 + tg;
    const int nb    = wn * 64 + tg;

    for (int i = 0; i < NK; i++) {
        cp_wait2();
        __syncthreads();
        if (i + 3 < NK) load_stage(i + 3, (i + 3) % STAGES);
        else            cp_commit();

        const uint32_t* sA = (const uint32_t*)(sm + (size_t)(i % STAGES) * STG_HALVES);
        const uint32_t* sB2 = sA + OP_HALVES / 2;

#pragma unroll
        for (int ks = 0; ks < 2; ks++) {
            const int kb2 = ks * 8;          // word offset (16 halves)
            uint32_t a[2][4], b[8][2];
#pragma unroll
            for (int mi = 0; mi < 2; mi++) {
                const int r = rbase + mi * 16;
                a[mi][0] = sA[(r)     * 20 + kb2 + tq];
                a[mi][1] = sA[(r + 8) * 20 + kb2 + tq];
                a[mi][2] = sA[(r)     * 20 + kb2 + tq + 4];
                a[mi][3] = sA[(r + 8) * 20 + kb2 + tq + 4];
            }
#pragma unroll
            for (int ni = 0; ni < 8; ni++) {
                b[ni][0] = sB2[(nb + ni * 8) * 20 + kb2 + tq];
                b[ni][1] = sB2[(nb + ni * 8) * 20 + kb2 + tq + 4];
            }
#pragma unroll
            for (int mi = 0; mi < 2; mi++)
#pragma unroll
                for (int ni = 0; ni < 8; ni++)
                    MMA_F16(acc[mi][ni], a[mi], b[ni]);
        }
    }

    // ---------------- epilogue ----------------------------------------------
#pragma unroll
    for (int mi = 0; mi < 2; mi++) {
#pragma unroll
        for (int h = 0; h < 2; h++) {
            const int m = bm + wm * 32 + mi * 16 + h * 8 + tg;
            if (EPI == 0) {
                const int sel = bn >> 11;
                const int nl0 = bn - sel * C_DIM + wn * 64 + 2 * tq;
#pragma unroll
                for (int ni = 0; ni < 8; ni++) {
                    const int nl = nl0 + ni * 8;
                    const int gn = bn + wn * 64 + ni * 8 + 2 * tq;
                    const float v0 = acc[mi][ni][2 * h]     + bias[gn];
                    const float v1 = acc[mi][ni][2 * h + 1] + bias[gn + 1];
                    if (sel == 0) {
                        const float u0 = gq[nl] * v0 + bq[nl];
                        const float u1 = gq[nl + 1] * v1 + bq[nl + 1];
                        *(__half2*)((__half*)O0 + (size_t)m * C_DIM + nl) =
                            __floats2half2_rn(u0 * u0, u1 * u1);
                    } else if (sel == 1) {
                        const float u0 = gk[nl] * v0 + bk[nl];
                        const float u1 = gk[nl + 1] * v1 + bk[nl + 1];
                        O1[(size_t)nl * T_DIM + m]       = __float2half_rn(u0 * u0);
                        O1[(size_t)(nl + 1) * T_DIM + m] = __float2half_rn(u1 * u1);
                    } else {
                        O2[(size_t)nl * T_DIM + m]       = __float2half_rn(v0);
                        O2[(size_t)(nl + 1) * T_DIM + m] = __float2half_rn(v1);
                    }
                }
            } else if (EPI == 1) {
#pragma unroll
                for (int ni = 0; ni < 8; ni++) {
                    const int n = bn + wn * 64 + ni * 8 + 2 * tq;
                    *(__half2*)((__half*)O0 + (size_t)m * N + n) =
                        __floats2half2_rn(acc[mi][ni][2 * h], acc[mi][ni][2 * h + 1]);
                }
            } else if (EPI == 2) {
#pragma unroll
                for (int ni = 0; ni < 8; ni++) {
                    const int n = bn + wn * 64 + ni * 8 + 2 * tq;
                    float2 o = { acc[mi][ni][2 * h], acc[mi][ni][2 * h + 1] };
                    *(float2*)((float*)O0 + (size_t)m * N + n) = o;
                }
            } else {
#pragma unroll
                for (int ni = 0; ni < 8; ni++) {
                    const int n = bn + wn * 64 + ni * 8 + 2 * tq;
                    float2 o = { acc[mi][ni][2 * h] + bias[n],
                                 acc[mi][ni][2 * h + 1] + bias[n + 1] };
                    *(float2*)((float*)O0 + (size_t)m * N + n) = o;
                }
            }
        }
    }
}

// ---------------- aux kernels ------------------------------------------------
__global__ void f2h_kernel(const float* __restrict__ in, __half* __restrict__ out, int n2)
{
    int i = blockIdx.x * blockDim.x + threadIdx.x;
    if (i < n2) {
        float2 v = ((const float2*)in)[i];
        ((__half2*)out)[i] = __floats2half2_rn(v.x, v.y);
    }
}

// out[j,i] = half(in[i,j]); in is [R, Cc] fp32
__global__ void transpose_h_kernel(const float* __restrict__ in, __half* __restrict__ out,
                                   int R, int Cc)
{
    __shared__ float tile[32][33];
    const int j0 = blockIdx.x * 32;
    const int i0 = blockIdx.y * 32;
#pragma unroll
    for (int k = 0; k < 32; k += 8)
        tile[threadIdx.y + k][threadIdx.x] =
            in[(size_t)(i0 + threadIdx.y + k) * Cc + j0 + threadIdx.x];
    __syncthreads();
#pragma unroll
    for (int k = 0; k < 32; k += 8)
        out[(size_t)(j0 + threadIdx.y + k) * R + i0 + threadIdx.x] =
            __float2half_rn(tile[threadIdx.x][threadIdx.y + k]);
}

// ksum[c] = sum_t kerkT[c, t]
__global__ __launch_bounds__(256)
void ksum_kernel()
{
    const int c = blockIdx.x;
    const __half2* row = (const __half2*)(g_kerkT + (size_t)c * T_DIM);
    float s = 0.f;
    for (int t = threadIdx.x; t < T_DIM / 2; t += 256) {
        float2 v = __half22float2(row[t]);
        s += v.x + v.y;
    }
    __shared__ float red[8];
#pragma unroll
    for (int off = 16; off; off >>= 1) s += __shfl_down_sync(0xffffffffu, s, off);
    if ((threadIdx.x & 31) == 0) red[threadIdx.x >> 5] = s;
    __syncthreads();
    if (threadIdx.x == 0) {
        float tot = 0.f;
#pragma unroll
        for (int w = 0; w < 8; w++) tot += red[w];
        g_ksum[c] = tot;
    }
}

// den[t] = kerq[t,:] . ksum
__global__ __launch_bounds__(256)
void den_kernel()
{
    const int t = blockIdx.x;
    const __half2* row = (const __half2*)(g_kerq + (size_t)t * C_DIM);
    const float2* ks = (const float2*)g_ksum;
    float s = 0.f;
    for (int c = threadIdx.x; c < C_DIM / 2; c += 256) {
        float2 v = __half22float2(row[c]);
        float2 k = ks[c];
        s += v.x * k.x + v.y * k.y;
    }
    __shared__ float red[8];
#pragma unroll
    for (int off = 16; off; off >>= 1) s += __shfl_down_sync(0xffffffffu, s, off);
    if ((threadIdx.x & 31) == 0) red[threadIdx.x >> 5] = s;
    __syncthreads();
    if (threadIdx.x == 0) {
        float tot = 0.f;
#pragma unroll
        for (int w = 0; w < 8; w++) tot += red[w];
        g_den[t] = tot;
    }
}

// zt[c,t] = half(num[t,c] / den[t])
__global__ void tdiv_kernel()
{
    __shared__ float tile[32][33];
    const int c  = blockIdx.x * 32 + threadIdx.x;
    const int by = blockIdx.y * 32;
#pragma unroll
    for (int i = 0; i < 32; i += 8) {
        int t = by + threadIdx.y + i;
        tile[threadIdx.y + i][threadIdx.x] = g_num[(size_t)t * C_DIM + c] / g_den[t];
    }
    __syncthreads();
    const int t2 = by + threadIdx.x;
#pragma unroll
    for (int i = 0; i < 32; i += 8) {
        int c2 = blockIdx.x * 32 + threadIdx.y + i;
        g_zt[(size_t)c2 * T_DIM + t2] = __float2half_rn(tile[threadIdx.x][threadIdx.y + i]);
    }
}

// ---------------- launch -----------------------------------------------------
extern "C" void kernel_launch(void* const* d_in, const int* in_sizes, int n_in,
                              void* d_out, int out_size)
{
    const float* x      = (const float*)d_in[0];
    const float* w_attn = (const float*)d_in[1];
    const float* b_attn = (const float*)d_in[2];
    const float* gq     = (const float*)d_in[3];
    const float* bq     = (const float*)d_in[4];
    const float* gk     = (const float*)d_in[5];
    const float* bk     = (const float*)d_in[6];
    const float* w_out  = (const float*)d_in[7];
    const float* b_out  = (const float*)d_in[8];
    float* out = (float*)d_out;

    __half *p_xh, *p_waT, *p_woT, *p_kerq, *p_kerkT, *p_vT, *p_kvT, *p_zt;
    float *p_num;
    cudaGetSymbolAddress((void**)&p_xh,    g_xh);
    cudaGetSymbolAddress((void**)&p_waT,   g_waT);
    cudaGetSymbolAddress((void**)&p_woT,   g_woT);
    cudaGetSymbolAddress((void**)&p_kerq,  g_kerq);
    cudaGetSymbolAddress((void**)&p_kerkT, g_kerkT);
    cudaGetSymbolAddress((void**)&p_vT,    g_vT);
    cudaGetSymbolAddress((void**)&p_kvT,   g_kvT);
    cudaGetSymbolAddress((void**)&p_zt,    g_zt);
    cudaGetSymbolAddress((void**)&p_num,   g_num);

    cudaFuncSetAttribute(mma_gemm<0>, cudaFuncAttributeMaxDynamicSharedMemorySize, SMEM_BYTES);
    cudaFuncSetAttribute(mma_gemm<1>, cudaFuncAttributeMaxDynamicSharedMemorySize, SMEM_BYTES);
    cudaFuncSetAttribute(mma_gemm<2>, cudaFuncAttributeMaxDynamicSharedMemorySize, SMEM_BYTES);
    cudaFuncSetAttribute(mma_gemm<3>, cudaFuncAttributeMaxDynamicSharedMemorySize, SMEM_BYTES);

    // prep: x -> half, weights -> transposed half
    f2h_kernel<<<(T_DIM * C_DIM / 2 + 255) / 256, 256>>>(x, p_xh, T_DIM * C_DIM / 2);
    {
        dim3 grid(3 * C_DIM / 32, C_DIM / 32);
        transpose_h_kernel<<<grid, dim3(32, 8)>>>(w_attn, p_waT, C_DIM, 3 * C_DIM);
    }
    {
        dim3 grid(C_DIM / 32, C_DIM / 32);
        transpose_h_kernel<<<grid, dim3(32, 8)>>>(w_out, p_woT, C_DIM, C_DIM);
    }

    // 1) qkv = x @ waT^T + b : kerq [T,C], kerkT [C,T], vT [C,T]
    {
        dim3 grid(3 * C_DIM / BN, T_DIM / BM);
        mma_gemm<0><<<grid, 256, SMEM_BYTES>>>(
            p_xh, p_waT, b_attn, p_kerq, p_kerkT, p_vT,
            gq, bq, gk, bk, 3 * C_DIM, C_DIM);
    }
    // 2) ksum, den
    ksum_kernel<<<C_DIM, 256>>>();
    den_kernel<<<T_DIM, 256>>>();
    // 3) kvT[d,c] = sum_t vT[d,t] kerkT[c,t]
    {
        dim3 grid(C_DIM / BN, C_DIM / BM);
        mma_gemm<1><<<grid, 256, SMEM_BYTES>>>(
            p_vT, p_kerkT, nullptr, p_kvT, nullptr, nullptr,
            nullptr, nullptr, nullptr, nullptr, C_DIM, T_DIM);
    }
    // 4) num[t,d] = sum_c kerq[t,c] kvT[d,c]   (fp32 out)
    {
        dim3 grid(C_DIM / BN, T_DIM / BM);
        mma_gemm<2><<<grid, 256, SMEM_BYTES>>>(
            p_kerq, p_kvT, nullptr, p_num, nullptr, nullptr,
            nullptr, nullptr, nullptr, nullptr, C_DIM, C_DIM);
    }
    // 5) zt = (num/den)^T as half (the transpose(1,2).view reinterpretation)
    {
        dim3 grid(C_DIM / 32, T_DIM / 32);
        tdiv_kernel<<<grid, dim3(32, 8)>>>();
    }
    // 6) out = view(zt,[T,C]) @ woT^T + b_out
    {
        dim3 grid(C_DIM / BN, T_DIM / BM);
        mma_gemm<3><<<grid, 256, SMEM_BYTES>>>(
            p_zt, p_woT, b_out, out, nullptr, nullptr,
            nullptr, nullptr, nullptr, nullptr, C_DIM, C_DIM);
    }
    (void)in_sizes; (void)n_in; (void)out_size;
}